// round 11
// baseline (speedup 1.0000x reference)
#include <cuda_runtime.h>
#include <cuda_fp16.h>
#include <cstdint>

// NoiseNet: out[e,:] = tanh( concat(nf[recv[e]], nf[send[e]]) @ W + b )
// Factored:  P[n][0:64]  = nf[n] @ W[0:64,:]  + b   (recv table, bias folded)
//            P[n][64:128]= nf[n] @ W[64:128,:]      (send table)
//            out[e]      = tanh( P[recv[e]][0:64] + P[send[e]][64:128] )
// P stored fp16. Edge kernel: 4 threads/edge, 4 independent 16B gathers per
// thread (MLP=4), 16 tanh, 4x STG.128.

#define D_FEAT 64
#define P_COLS 128
#define MAX_NODES 50000

#define PM 128              // nodes per precompute CTA
#define ROW_B 144           // 64 halfs (128B) + 16B pad: conflict-free LDSM
#define PRE_SMEM (2 * PM * ROW_B)

__device__ __half g_P[MAX_NODES * P_COLS];   // 12.8 MB node table (L2-resident)

__device__ __forceinline__ uint32_t smem_u32(const void* p) {
    uint32_t a;
    asm("{ .reg .u64 t; cvta.to.shared.u64 t, %1; cvt.u32.u64 %0, t; }" : "=r"(a) : "l"(p));
    return a;
}
__device__ __forceinline__ float tanh_fast(float x) {
    float y;
    asm("tanh.approx.f32 %0, %1;" : "=f"(y) : "f"(x));
    return y;
}
__device__ __forceinline__ void ldsm_x4(uint32_t& r0, uint32_t& r1,
                                        uint32_t& r2, uint32_t& r3, uint32_t addr) {
    asm volatile("ldmatrix.sync.aligned.m8n8.x4.shared.b16 {%0,%1,%2,%3}, [%4];"
                 : "=r"(r0), "=r"(r1), "=r"(r2), "=r"(r3) : "r"(addr));
}
__device__ __forceinline__ void mma_16x8x16_f16(float c[4], const uint32_t a[4],
                                                uint32_t b0, uint32_t b1) {
    asm volatile(
        "mma.sync.aligned.m16n8k16.row.col.f32.f16.f16.f32 "
        "{%0,%1,%2,%3}, {%4,%5,%6,%7}, {%8,%9}, {%0,%1,%2,%3};"
        : "+f"(c[0]), "+f"(c[1]), "+f"(c[2]), "+f"(c[3])
        : "r"(a[0]), "r"(a[1]), "r"(a[2]), "r"(a[3]), "r"(b0), "r"(b1));
}
__device__ __forceinline__ uint4 ldg_nc_128(const void* p) {
    uint4 v;
    asm volatile("ld.global.nc.v4.u32 {%0,%1,%2,%3}, [%4];"
                 : "=r"(v.x), "=r"(v.y), "=r"(v.z), "=r"(v.w) : "l"(p));
    return v;
}

// ---- Precompute: P[m0..m0+128][128] = nf @ [Wtop | Wbot] (+bias on cols<64) ----
__global__ __launch_bounds__(256)
void precompute_P_kernel(const float* __restrict__ nf,
                         const float* __restrict__ W,
                         const float* __restrict__ bias,
                         int n_nodes)
{
    extern __shared__ char smem[];
    char* As = smem;                    // [128 rows][ROW_B]  fp16 node feats
    char* Bt = smem + PM * ROW_B;       // [128 n][ROW_B]     fp16 Wcat, n-major

    const int tid = threadIdx.x;
    const int wid = tid >> 5;
    const int lid = tid & 31;
    const int m0  = blockIdx.x * PM;
    const uint32_t a_addr  = smem_u32(As);
    const uint32_t bt_addr = smem_u32(Bt);

    // Stage Bt[n][k]: n<64 -> W[k][n]; n>=64 -> W[64+k][n-64]
    for (int c = tid; c < P_COLS * 8; c += 256) {
        const int n  = c >> 3;
        const int kq = c & 7;
        const int off  = (n >= 64) ? 64 : 0;
        const int ncol = n & 63;
        __half2 h[4];
        #pragma unroll
        for (int j = 0; j < 4; j++)
            h[j] = __floats2half2_rn(W[(off + kq * 8 + 2 * j) * 64 + ncol],
                                     W[(off + kq * 8 + 2 * j + 1) * 64 + ncol]);
        *reinterpret_cast<uint4*>(Bt + n * ROW_B + kq * 16)
            = *reinterpret_cast<uint4*>(h);
    }

    // Stage A: rows = nodes m0..m0+127, 64 halfs each (convert f32->f16)
    {
        const float4* nf4 = reinterpret_cast<const float4*>(nf);
        for (int c = tid; c < PM * 8; c += 256) {
            const int r  = c >> 3;
            const int kq = c & 7;
            int node = m0 + r;
            if (node >= n_nodes) node = n_nodes - 1;
            float4 v0 = nf4[node * 16 + kq * 2];
            float4 v1 = nf4[node * 16 + kq * 2 + 1];
            __half2 h[4] = { __floats2half2_rn(v0.x, v0.y),
                             __floats2half2_rn(v0.z, v0.w),
                             __floats2half2_rn(v1.x, v1.y),
                             __floats2half2_rn(v1.z, v1.w) };
            *reinterpret_cast<uint4*>(As + r * ROW_B + kq * 16)
                = *reinterpret_cast<uint4*>(h);
        }
    }
    __syncthreads();

    // Warp tiling: wm = wid&3 rows 32*wm..+32; wn = wid>>2 cols 64*wn..+64
    const int wm = wid & 3;
    const int wn = wid >> 2;
    const int g  = lid >> 2;
    const int cc = lid & 3;
    const int r16 = lid & 15;
    const int sel = lid >> 4;

    float acc[2][8][4];
    #pragma unroll
    for (int mt = 0; mt < 2; mt++)
        #pragma unroll
        for (int nt = 0; nt < 8; nt++)
            #pragma unroll
            for (int r = 0; r < 4; r++)
                acc[mt][nt][r] = 0.0f;

    uint32_t aOff[2];
    #pragma unroll
    for (int mt = 0; mt < 2; mt++)
        aOff[mt] = (uint32_t)((wm * 32 + mt * 16 + r16) * ROW_B)
                 + (uint32_t)(sel * 16);

    const int bn_lane = ((lid >> 4) & 1) * 8 + (lid & 7);
    const uint32_t bk16 = (uint32_t)(((lid >> 3) & 1) * 16);

    #pragma unroll
    for (int s = 0; s < 4; s++) {                 // K=64, 16 per step
        const uint32_t koff = (uint32_t)s * 32u;
        uint32_t a[2][4];
        #pragma unroll
        for (int mt = 0; mt < 2; mt++)
            ldsm_x4(a[mt][0], a[mt][1], a[mt][2], a[mt][3],
                    a_addr + aOff[mt] + koff);
        #pragma unroll
        for (int p = 0; p < 4; p++) {
            uint32_t r0, r1, r2, r3;
            const uint32_t bF = bt_addr
                + (uint32_t)((wn * 64 + p * 16 + bn_lane) * ROW_B) + bk16;
            ldsm_x4(r0, r1, r2, r3, bF + koff);
            #pragma unroll
            for (int mt = 0; mt < 2; mt++) {
                mma_16x8x16_f16(acc[mt][2 * p + 0], a[mt], r0, r1);
                mma_16x8x16_f16(acc[mt][2 * p + 1], a[mt], r2, r3);
            }
        }
    }

    // Epilogue: +bias on cols<64, store fp16 into g_P
    #pragma unroll
    for (int nt = 0; nt < 8; nt++) {
        const int col = wn * 64 + nt * 8 + 2 * cc;
        float2 bj = make_float2(0.f, 0.f);
        if (col < 64) bj = *reinterpret_cast<const float2*>(&bias[col]);
        #pragma unroll
        for (int mt = 0; mt < 2; mt++) {
            const int node0 = m0 + wm * 32 + mt * 16 + g;
            if (node0 < n_nodes) {
                __half2 h = __floats2half2_rn(acc[mt][nt][0] + bj.x,
                                              acc[mt][nt][1] + bj.y);
                *reinterpret_cast<__half2*>(&g_P[node0 * P_COLS + col]) = h;
            }
            const int node1 = node0 + 8;
            if (node1 < n_nodes) {
                __half2 h = __floats2half2_rn(acc[mt][nt][2] + bj.x,
                                              acc[mt][nt][3] + bj.y);
                *reinterpret_cast<__half2*>(&g_P[node1 * P_COLS + col]) = h;
            }
        }
    }
}

// ---- Edge kernel: 4 threads/edge, 16 cols each; MLP=4 gathers/thread ----
__global__ __launch_bounds__(256)
void edge_kernel(const int* __restrict__ senders,
                 const int* __restrict__ receivers,
                 float* __restrict__ out,
                 int n_edges)
{
    const int t = blockIdx.x * 256 + threadIdx.x;
    const int e = t >> 2;
    const int sub = t & 3;             // 16 cols per thread
    if (e >= n_edges) return;

    const int r = __ldg(&receivers[e]);
    const int s = __ldg(&senders[e]);

    // 4 independent 16B loads (2 per table half) — all in flight together
    const __half* pr = &g_P[r * P_COLS + sub * 16];
    const __half* ps = &g_P[s * P_COLS + 64 + sub * 16];
    uint4 ar0 = ldg_nc_128(pr);
    uint4 ar1 = ldg_nc_128(pr + 8);
    uint4 as0 = ldg_nc_128(ps);
    uint4 as1 = ldg_nc_128(ps + 8);

    float4 o[4];
    {
        const __half2* hr0 = reinterpret_cast<const __half2*>(&ar0);
        const __half2* hs0 = reinterpret_cast<const __half2*>(&as0);
        #pragma unroll
        for (int i = 0; i < 4; i++) {
            float2 fr = __half22float2(hr0[i]);
            float2 fs = __half22float2(hs0[i]);
            float* dst = reinterpret_cast<float*>(&o[i >> 1]) + (i & 1) * 2;
            dst[0] = tanh_fast(fr.x + fs.x);
            dst[1] = tanh_fast(fr.y + fs.y);
        }
        const __half2* hr1 = reinterpret_cast<const __half2*>(&ar1);
        const __half2* hs1 = reinterpret_cast<const __half2*>(&as1);
        #pragma unroll
        for (int i = 0; i < 4; i++) {
            float2 fr = __half22float2(hr1[i]);
            float2 fs = __half22float2(hs1[i]);
            float* dst = reinterpret_cast<float*>(&o[2 + (i >> 1)]) + (i & 1) * 2;
            dst[0] = tanh_fast(fr.x + fs.x);
            dst[1] = tanh_fast(fr.y + fs.y);
        }
    }

    float4* op = reinterpret_cast<float4*>(&out[(size_t)e * 64 + sub * 16]);
    op[0] = o[0];
    op[1] = o[1];
    op[2] = o[2];
    op[3] = o[3];
}

extern "C" void kernel_launch(void* const* d_in, const int* in_sizes, int n_in,
                              void* d_out, int out_size)
{
    const float* node_feats = (const float*)d_in[0];
    const int*   senders    = (const int*)d_in[1];
    const int*   receivers  = (const int*)d_in[2];
    const float* W          = (const float*)d_in[3];
    const float* b          = (const float*)d_in[4];
    float*       out        = (float*)d_out;

    const int n_nodes = in_sizes[0] / D_FEAT;
    const int n_edges = in_sizes[1];

    static bool attr_set = false;
    if (!attr_set) {
        cudaFuncSetAttribute(precompute_P_kernel,
                             cudaFuncAttributeMaxDynamicSharedMemorySize, PRE_SMEM);
        attr_set = true;
    }

    const int pre_grid = (n_nodes + PM - 1) / PM;
    precompute_P_kernel<<<pre_grid, 256, PRE_SMEM>>>(node_feats, W, b, n_nodes);

    const int edge_grid = (n_edges * 4 + 255) / 256;
    edge_kernel<<<edge_grid, 256>>>(senders, receivers, out, n_edges);
}

// round 12
// speedup vs baseline: 1.4406x; 1.4406x over previous
#include <cuda_runtime.h>
#include <cuda_fp16.h>
#include <cstdint>

// NoiseNet: out[e,:] = tanh( concat(nf[recv[e]], nf[send[e]]) @ W + b )
// Factored:  P[n][0:64]  = nf[n] @ W[0:64,:]  + b   (recv table, bias folded)
//            P[n][64:128]= nf[n] @ W[64:128,:]      (send table)
//            out[e]      = tanh( P[recv[e]][0:64] + P[send[e]][64:128] )
// P stored fp16. Edge kernel: warp-cooperative gather — each LDG's lanes cover
// whole 128B lines (2 gather wavefronts/edge, the minimum), shfl exchange.

#define D_FEAT 64
#define P_COLS 128
#define MAX_NODES 50000

#define PM 128              // nodes per precompute CTA
#define ROW_B 144           // 64 halfs (128B) + 16B pad: conflict-free LDSM
#define PRE_SMEM (2 * PM * ROW_B)

__device__ __half g_P[MAX_NODES * P_COLS];   // 12.8 MB node table (L2-resident)

__device__ __forceinline__ uint32_t smem_u32(const void* p) {
    uint32_t a;
    asm("{ .reg .u64 t; cvta.to.shared.u64 t, %1; cvt.u32.u64 %0, t; }" : "=r"(a) : "l"(p));
    return a;
}
__device__ __forceinline__ float tanh_fast(float x) {
    float y;
    asm("tanh.approx.f32 %0, %1;" : "=f"(y) : "f"(x));
    return y;
}
__device__ __forceinline__ void ldsm_x4(uint32_t& r0, uint32_t& r1,
                                        uint32_t& r2, uint32_t& r3, uint32_t addr) {
    asm volatile("ldmatrix.sync.aligned.m8n8.x4.shared.b16 {%0,%1,%2,%3}, [%4];"
                 : "=r"(r0), "=r"(r1), "=r"(r2), "=r"(r3) : "r"(addr));
}
__device__ __forceinline__ void mma_16x8x16_f16(float c[4], const uint32_t a[4],
                                                uint32_t b0, uint32_t b1) {
    asm volatile(
        "mma.sync.aligned.m16n8k16.row.col.f32.f16.f16.f32 "
        "{%0,%1,%2,%3}, {%4,%5,%6,%7}, {%8,%9}, {%0,%1,%2,%3};"
        : "+f"(c[0]), "+f"(c[1]), "+f"(c[2]), "+f"(c[3])
        : "r"(a[0]), "r"(a[1]), "r"(a[2]), "r"(a[3]), "r"(b0), "r"(b1));
}
__device__ __forceinline__ uint4 ldg_nc_128(const void* p) {
    uint4 v;
    asm volatile("ld.global.nc.v4.u32 {%0,%1,%2,%3}, [%4];"
                 : "=r"(v.x), "=r"(v.y), "=r"(v.z), "=r"(v.w) : "l"(p));
    return v;
}

// ---- Precompute: P[m0..m0+128][128] = nf @ [Wtop | Wbot] (+bias on cols<64) ----
__global__ __launch_bounds__(256)
void precompute_P_kernel(const float* __restrict__ nf,
                         const float* __restrict__ W,
                         const float* __restrict__ bias,
                         int n_nodes)
{
    extern __shared__ char smem[];
    char* As = smem;                    // [128 rows][ROW_B]  fp16 node feats
    char* Bt = smem + PM * ROW_B;       // [128 n][ROW_B]     fp16 Wcat, n-major

    const int tid = threadIdx.x;
    const int wid = tid >> 5;
    const int lid = tid & 31;
    const int m0  = blockIdx.x * PM;
    const uint32_t a_addr  = smem_u32(As);
    const uint32_t bt_addr = smem_u32(Bt);

    // Stage Bt[n][k]: n<64 -> W[k][n]; n>=64 -> W[64+k][n-64]
    for (int c = tid; c < P_COLS * 8; c += 256) {
        const int n  = c >> 3;
        const int kq = c & 7;
        const int off  = (n >= 64) ? 64 : 0;
        const int ncol = n & 63;
        __half2 h[4];
        #pragma unroll
        for (int j = 0; j < 4; j++)
            h[j] = __floats2half2_rn(W[(off + kq * 8 + 2 * j) * 64 + ncol],
                                     W[(off + kq * 8 + 2 * j + 1) * 64 + ncol]);
        *reinterpret_cast<uint4*>(Bt + n * ROW_B + kq * 16)
            = *reinterpret_cast<uint4*>(h);
    }

    // Stage A: rows = nodes m0..m0+127, 64 halfs each (convert f32->f16)
    {
        const float4* nf4 = reinterpret_cast<const float4*>(nf);
        for (int c = tid; c < PM * 8; c += 256) {
            const int r  = c >> 3;
            const int kq = c & 7;
            int node = m0 + r;
            if (node >= n_nodes) node = n_nodes - 1;
            float4 v0 = nf4[node * 16 + kq * 2];
            float4 v1 = nf4[node * 16 + kq * 2 + 1];
            __half2 h[4] = { __floats2half2_rn(v0.x, v0.y),
                             __floats2half2_rn(v0.z, v0.w),
                             __floats2half2_rn(v1.x, v1.y),
                             __floats2half2_rn(v1.z, v1.w) };
            *reinterpret_cast<uint4*>(As + r * ROW_B + kq * 16)
                = *reinterpret_cast<uint4*>(h);
        }
    }
    __syncthreads();

    // Warp tiling: wm = wid&3 rows 32*wm..+32; wn = wid>>2 cols 64*wn..+64
    const int wm = wid & 3;
    const int wn = wid >> 2;
    const int g  = lid >> 2;
    const int cc = lid & 3;
    const int r16 = lid & 15;
    const int sel = lid >> 4;

    float acc[2][8][4];
    #pragma unroll
    for (int mt = 0; mt < 2; mt++)
        #pragma unroll
        for (int nt = 0; nt < 8; nt++)
            #pragma unroll
            for (int r = 0; r < 4; r++)
                acc[mt][nt][r] = 0.0f;

    uint32_t aOff[2];
    #pragma unroll
    for (int mt = 0; mt < 2; mt++)
        aOff[mt] = (uint32_t)((wm * 32 + mt * 16 + r16) * ROW_B)
                 + (uint32_t)(sel * 16);

    const int bn_lane = ((lid >> 4) & 1) * 8 + (lid & 7);
    const uint32_t bk16 = (uint32_t)(((lid >> 3) & 1) * 16);

    #pragma unroll
    for (int s = 0; s < 4; s++) {                 // K=64, 16 per step
        const uint32_t koff = (uint32_t)s * 32u;
        uint32_t a[2][4];
        #pragma unroll
        for (int mt = 0; mt < 2; mt++)
            ldsm_x4(a[mt][0], a[mt][1], a[mt][2], a[mt][3],
                    a_addr + aOff[mt] + koff);
        #pragma unroll
        for (int p = 0; p < 4; p++) {
            uint32_t r0, r1, r2, r3;
            const uint32_t bF = bt_addr
                + (uint32_t)((wn * 64 + p * 16 + bn_lane) * ROW_B) + bk16;
            ldsm_x4(r0, r1, r2, r3, bF + koff);
            #pragma unroll
            for (int mt = 0; mt < 2; mt++) {
                mma_16x8x16_f16(acc[mt][2 * p + 0], a[mt], r0, r1);
                mma_16x8x16_f16(acc[mt][2 * p + 1], a[mt], r2, r3);
            }
        }
    }

    // Epilogue: +bias on cols<64, store fp16 into g_P
    #pragma unroll
    for (int nt = 0; nt < 8; nt++) {
        const int col = wn * 64 + nt * 8 + 2 * cc;
        float2 bj = make_float2(0.f, 0.f);
        if (col < 64) bj = *reinterpret_cast<const float2*>(&bias[col]);
        #pragma unroll
        for (int mt = 0; mt < 2; mt++) {
            const int node0 = m0 + wm * 32 + mt * 16 + g;
            if (node0 < n_nodes) {
                __half2 h = __floats2half2_rn(acc[mt][nt][0] + bj.x,
                                              acc[mt][nt][1] + bj.y);
                *reinterpret_cast<__half2*>(&g_P[node0 * P_COLS + col]) = h;
            }
            const int node1 = node0 + 8;
            if (node1 < n_nodes) {
                __half2 h = __floats2half2_rn(acc[mt][nt][2] + bj.x,
                                              acc[mt][nt][3] + bj.y);
                *reinterpret_cast<__half2*>(&g_P[node1 * P_COLS + col]) = h;
            }
        }
    }
}

// ---- Edge kernel: warp = 8 edges, line-coherent gathers ----
// Round r serves edges base+2r, base+2r+1.
// Lane groups g=lane>>3: g0 recv(e), g1 send(e), g2 recv(e+1), g3 send(e+1).
// Each 8-lane group's 16B loads cover ONE 128B line -> 4 lines/instr (min).
__global__ __launch_bounds__(256)
void edge_kernel(const int* __restrict__ senders,
                 const int* __restrict__ receivers,
                 float* __restrict__ out,
                 int n_edges)
{
    const int lane = threadIdx.x & 31;
    const int warp = (blockIdx.x * 256 + threadIdx.x) >> 5;
    const int base = warp * 8;
    if (base >= n_edges) return;

    // lanes 0-7: recv indices of the warp's 8 edges; lanes 8-15: send indices
    int idx = 0;
    {
        int e = base + (lane & 7);
        if (e >= n_edges) e = n_edges - 1;
        if (lane < 8)       idx = receivers[e];
        else if (lane < 16) idx = senders[e];
    }

    const int g = lane >> 3;
    const int c = lane & 7;                  // 16B chunk within the 128B line
    const int odd = g & 1;                   // 0: recv-carrier, 1: send-carrier
    const int epair = g >> 1;                // 0 or 1 within the round's pair
    const int half_off = odd ? 64 : 0;

    // Issue all 4 rounds' gathers back-to-back (MLP=4, 4 lines per instr)
    uint4 v[4];
    #pragma unroll
    for (int r = 0; r < 4; r++) {
        const int src = (odd << 3) + 2 * r + epair;   // idx-holder lane
        const int node = __shfl_sync(0xffffffffu, idx, src);
        v[r] = ldg_nc_128(&g_P[node * P_COLS + half_off + c * 8]);
    }

    // Consume: exchange exactly the 2 words each lane needs from its partner
    #pragma unroll
    for (int r = 0; r < 4; r++) {
        // even lane supplies its words 2,3 (recv cols 8c+4..7) and receives
        // partner's words 0,1 (send cols 8c+0..3); odd lane vice versa.
        const uint32_t s0 = odd ? v[r].x : v[r].z;
        const uint32_t s1 = odd ? v[r].y : v[r].w;
        const uint32_t p0 = __shfl_xor_sync(0xffffffffu, s0, 8);
        const uint32_t p1 = __shfl_xor_sync(0xffffffffu, s1, 8);

        const uint32_t m0 = odd ? v[r].z : v[r].x;   // own contribution
        const uint32_t m1 = odd ? v[r].w : v[r].y;

        const float2 a0 = __half22float2(*reinterpret_cast<const __half2*>(&m0));
        const float2 b0 = __half22float2(*reinterpret_cast<const __half2*>(&p0));
        const float2 a1 = __half22float2(*reinterpret_cast<const __half2*>(&m1));
        const float2 b1 = __half22float2(*reinterpret_cast<const __half2*>(&p1));

        float4 o;
        o.x = tanh_fast(a0.x + b0.x);
        o.y = tanh_fast(a0.y + b0.y);
        o.z = tanh_fast(a1.x + b1.x);
        o.w = tanh_fast(a1.y + b1.y);

        const int e = base + 2 * r + epair;
        if (e < n_edges) {
            // even lane: cols 8c..8c+3 ; odd lane: cols 8c+4..8c+7
            float* dst = out + (size_t)e * 64 + c * 8 + (odd ? 4 : 0);
            *reinterpret_cast<float4*>(dst) = o;
        }
    }
}

extern "C" void kernel_launch(void* const* d_in, const int* in_sizes, int n_in,
                              void* d_out, int out_size)
{
    const float* node_feats = (const float*)d_in[0];
    const int*   senders    = (const int*)d_in[1];
    const int*   receivers  = (const int*)d_in[2];
    const float* W          = (const float*)d_in[3];
    const float* b          = (const float*)d_in[4];
    float*       out        = (float*)d_out;

    const int n_nodes = in_sizes[0] / D_FEAT;
    const int n_edges = in_sizes[1];

    static bool attr_set = false;
    if (!attr_set) {
        cudaFuncSetAttribute(precompute_P_kernel,
                             cudaFuncAttributeMaxDynamicSharedMemorySize, PRE_SMEM);
        attr_set = true;
    }

    const int pre_grid = (n_nodes + PM - 1) / PM;
    precompute_P_kernel<<<pre_grid, 256, PRE_SMEM>>>(node_feats, W, b, n_nodes);

    const int warps_needed = (n_edges + 7) / 8;
    const int edge_grid = (warps_needed + 7) / 8;     // 8 warps per block
    edge_kernel<<<edge_grid, 256>>>(senders, receivers, out, n_edges);
}

// round 13
// speedup vs baseline: 1.6360x; 1.1356x over previous
#include <cuda_runtime.h>
#include <cuda_fp16.h>
#include <cstdint>

// NoiseNet: out[e,:] = tanh( concat(nf[recv[e]], nf[send[e]]) @ W + b )
// Factored:  P[n][0:64]  = nf[n] @ W[0:64,:]  + b   (recv table, bias folded)
//            P[n][64:128]= nf[n] @ W[64:128,:]      (send table)
//            out[e]      = tanh( P[recv[e]][0:64] + P[send[e]][64:128] )
// P fp16. Edge kernel: warp-cooperative line-coherent gather (R12).
// R13: precompute epilogue stages through SMEM -> coalesced 16B stores;
//      edge out stores use .cs streaming hint.

#define D_FEAT 64
#define P_COLS 128
#define MAX_NODES 50000

#define PM 128              // nodes per precompute CTA
#define ROW_B 144           // 64 halfs (128B) + 16B pad: conflict-free LDSM
#define ROW_PS 136          // halfs; 272B row stride for staging tile
#define PRE_SMEM (2 * PM * ROW_B)   // 36864 B (>= PM*ROW_PS*2 = 34816 B)

__device__ __half g_P[MAX_NODES * P_COLS];   // 12.8 MB node table (L2-resident)

__device__ __forceinline__ uint32_t smem_u32(const void* p) {
    uint32_t a;
    asm("{ .reg .u64 t; cvta.to.shared.u64 t, %1; cvt.u32.u64 %0, t; }" : "=r"(a) : "l"(p));
    return a;
}
__device__ __forceinline__ float tanh_fast(float x) {
    float y;
    asm("tanh.approx.f32 %0, %1;" : "=f"(y) : "f"(x));
    return y;
}
__device__ __forceinline__ void ldsm_x4(uint32_t& r0, uint32_t& r1,
                                        uint32_t& r2, uint32_t& r3, uint32_t addr) {
    asm volatile("ldmatrix.sync.aligned.m8n8.x4.shared.b16 {%0,%1,%2,%3}, [%4];"
                 : "=r"(r0), "=r"(r1), "=r"(r2), "=r"(r3) : "r"(addr));
}
__device__ __forceinline__ void mma_16x8x16_f16(float c[4], const uint32_t a[4],
                                                uint32_t b0, uint32_t b1) {
    asm volatile(
        "mma.sync.aligned.m16n8k16.row.col.f32.f16.f16.f32 "
        "{%0,%1,%2,%3}, {%4,%5,%6,%7}, {%8,%9}, {%0,%1,%2,%3};"
        : "+f"(c[0]), "+f"(c[1]), "+f"(c[2]), "+f"(c[3])
        : "r"(a[0]), "r"(a[1]), "r"(a[2]), "r"(a[3]), "r"(b0), "r"(b1));
}
__device__ __forceinline__ uint4 ldg_nc_128(const void* p) {
    uint4 v;
    asm volatile("ld.global.nc.v4.u32 {%0,%1,%2,%3}, [%4];"
                 : "=r"(v.x), "=r"(v.y), "=r"(v.z), "=r"(v.w) : "l"(p));
    return v;
}
__device__ __forceinline__ void stg_cs_128(void* p, float4 v) {
    asm volatile("st.global.cs.v4.f32 [%0], {%1,%2,%3,%4};"
                 :: "l"(p), "f"(v.x), "f"(v.y), "f"(v.z), "f"(v.w) : "memory");
}

// ---- Precompute: P[m0..m0+128][128] = nf @ [Wtop | Wbot] (+bias on cols<64) ----
__global__ __launch_bounds__(256)
void precompute_P_kernel(const float* __restrict__ nf,
                         const float* __restrict__ W,
                         const float* __restrict__ bias,
                         int n_nodes)
{
    extern __shared__ char smem[];
    char* As = smem;                    // [128 rows][ROW_B]  fp16 node feats
    char* Bt = smem + PM * ROW_B;       // [128 n][ROW_B]     fp16 Wcat, n-major
    __half* Ps = reinterpret_cast<__half*>(smem);  // staging overlay (after MMA)

    const int tid = threadIdx.x;
    const int wid = tid >> 5;
    const int lid = tid & 31;
    const int m0  = blockIdx.x * PM;
    const uint32_t a_addr  = smem_u32(As);
    const uint32_t bt_addr = smem_u32(Bt);

    // Stage Bt[n][k]: n<64 -> W[k][n]; n>=64 -> W[64+k][n-64]
    for (int c = tid; c < P_COLS * 8; c += 256) {
        const int n  = c >> 3;
        const int kq = c & 7;
        const int off  = (n >= 64) ? 64 : 0;
        const int ncol = n & 63;
        __half2 h[4];
        #pragma unroll
        for (int j = 0; j < 4; j++)
            h[j] = __floats2half2_rn(W[(off + kq * 8 + 2 * j) * 64 + ncol],
                                     W[(off + kq * 8 + 2 * j + 1) * 64 + ncol]);
        *reinterpret_cast<uint4*>(Bt + n * ROW_B + kq * 16)
            = *reinterpret_cast<uint4*>(h);
    }

    // Stage A: rows = nodes m0..m0+127 (convert f32->f16)
    {
        const float4* nf4 = reinterpret_cast<const float4*>(nf);
        for (int c = tid; c < PM * 8; c += 256) {
            const int r  = c >> 3;
            const int kq = c & 7;
            int node = m0 + r;
            if (node >= n_nodes) node = n_nodes - 1;
            float4 v0 = nf4[node * 16 + kq * 2];
            float4 v1 = nf4[node * 16 + kq * 2 + 1];
            __half2 h[4] = { __floats2half2_rn(v0.x, v0.y),
                             __floats2half2_rn(v0.z, v0.w),
                             __floats2half2_rn(v1.x, v1.y),
                             __floats2half2_rn(v1.z, v1.w) };
            *reinterpret_cast<uint4*>(As + r * ROW_B + kq * 16)
                = *reinterpret_cast<uint4*>(h);
        }
    }
    __syncthreads();

    // Warp tiling: wm = wid&3 rows 32*wm..+32; wn = wid>>2 cols 64*wn..+64
    const int wm = wid & 3;
    const int wn = wid >> 2;
    const int g  = lid >> 2;
    const int cc = lid & 3;
    const int r16 = lid & 15;
    const int sel = lid >> 4;

    float acc[2][8][4];
    #pragma unroll
    for (int mt = 0; mt < 2; mt++)
        #pragma unroll
        for (int nt = 0; nt < 8; nt++)
            #pragma unroll
            for (int r = 0; r < 4; r++)
                acc[mt][nt][r] = 0.0f;

    uint32_t aOff[2];
    #pragma unroll
    for (int mt = 0; mt < 2; mt++)
        aOff[mt] = (uint32_t)((wm * 32 + mt * 16 + r16) * ROW_B)
                 + (uint32_t)(sel * 16);

    const int bn_lane = ((lid >> 4) & 1) * 8 + (lid & 7);
    const uint32_t bk16 = (uint32_t)(((lid >> 3) & 1) * 16);

    #pragma unroll
    for (int s = 0; s < 4; s++) {                 // K=64, 16 per step
        const uint32_t koff = (uint32_t)s * 32u;
        uint32_t a[2][4];
        #pragma unroll
        for (int mt = 0; mt < 2; mt++)
            ldsm_x4(a[mt][0], a[mt][1], a[mt][2], a[mt][3],
                    a_addr + aOff[mt] + koff);
        #pragma unroll
        for (int p = 0; p < 4; p++) {
            uint32_t r0, r1, r2, r3;
            const uint32_t bF = bt_addr
                + (uint32_t)((wn * 64 + p * 16 + bn_lane) * ROW_B) + bk16;
            ldsm_x4(r0, r1, r2, r3, bF + koff);
            #pragma unroll
            for (int mt = 0; mt < 2; mt++) {
                mma_16x8x16_f16(acc[mt][2 * p + 0], a[mt], r0, r1);
                mma_16x8x16_f16(acc[mt][2 * p + 1], a[mt], r2, r3);
            }
        }
    }

    // ---- Epilogue pass 1: bias + convert, into SMEM staging tile ----
    __syncthreads();   // all warps done reading As/Bt; safe to overwrite
    #pragma unroll
    for (int nt = 0; nt < 8; nt++) {
        const int col = wn * 64 + nt * 8 + 2 * cc;
        float2 bj = make_float2(0.f, 0.f);
        if (col < 64) bj = *reinterpret_cast<const float2*>(&bias[col]);
        #pragma unroll
        for (int mt = 0; mt < 2; mt++) {
            const int row0 = wm * 32 + mt * 16 + g;
            __half2 h0 = __floats2half2_rn(acc[mt][nt][0] + bj.x,
                                           acc[mt][nt][1] + bj.y);
            __half2 h1 = __floats2half2_rn(acc[mt][nt][2] + bj.x,
                                           acc[mt][nt][3] + bj.y);
            *reinterpret_cast<__half2*>(&Ps[row0 * ROW_PS + col]) = h0;
            *reinterpret_cast<__half2*>(&Ps[(row0 + 8) * ROW_PS + col]) = h1;
        }
    }
    __syncthreads();

    // ---- Epilogue pass 2: coalesced 16B stores to g_P ----
    for (int c = tid; c < PM * 16; c += 256) {
        const int r = c >> 4;
        const int q = c & 15;
        const int node = m0 + r;
        if (node < n_nodes) {
            *reinterpret_cast<uint4*>(&g_P[node * P_COLS + q * 8])
                = *reinterpret_cast<const uint4*>(&Ps[r * ROW_PS + q * 8]);
        }
    }
}

// ---- Edge kernel: warp = 8 edges, line-coherent gathers (R12) ----
__global__ __launch_bounds__(256)
void edge_kernel(const int* __restrict__ senders,
                 const int* __restrict__ receivers,
                 float* __restrict__ out,
                 int n_edges)
{
    const int lane = threadIdx.x & 31;
    const int warp = (blockIdx.x * 256 + threadIdx.x) >> 5;
    const int base = warp * 8;
    if (base >= n_edges) return;

    int idx = 0;
    {
        int e = base + (lane & 7);
        if (e >= n_edges) e = n_edges - 1;
        if (lane < 8)       idx = receivers[e];
        else if (lane < 16) idx = senders[e];
    }

    const int g = lane >> 3;
    const int c = lane & 7;
    const int odd = g & 1;
    const int epair = g >> 1;
    const int half_off = odd ? 64 : 0;

    uint4 v[4];
    #pragma unroll
    for (int r = 0; r < 4; r++) {
        const int src = (odd << 3) + 2 * r + epair;
        const int node = __shfl_sync(0xffffffffu, idx, src);
        v[r] = ldg_nc_128(&g_P[node * P_COLS + half_off + c * 8]);
    }

    #pragma unroll
    for (int r = 0; r < 4; r++) {
        const uint32_t s0 = odd ? v[r].x : v[r].z;
        const uint32_t s1 = odd ? v[r].y : v[r].w;
        const uint32_t p0 = __shfl_xor_sync(0xffffffffu, s0, 8);
        const uint32_t p1 = __shfl_xor_sync(0xffffffffu, s1, 8);

        const uint32_t m0 = odd ? v[r].z : v[r].x;
        const uint32_t m1 = odd ? v[r].w : v[r].y;

        const float2 a0 = __half22float2(*reinterpret_cast<const __half2*>(&m0));
        const float2 b0 = __half22float2(*reinterpret_cast<const __half2*>(&p0));
        const float2 a1 = __half22float2(*reinterpret_cast<const __half2*>(&m1));
        const float2 b1 = __half22float2(*reinterpret_cast<const __half2*>(&p1));

        float4 o;
        o.x = tanh_fast(a0.x + b0.x);
        o.y = tanh_fast(a0.y + b0.y);
        o.z = tanh_fast(a1.x + b1.x);
        o.w = tanh_fast(a1.y + b1.y);

        const int e = base + 2 * r + epair;
        if (e < n_edges) {
            float* dst = out + (size_t)e * 64 + c * 8 + (odd ? 4 : 0);
            stg_cs_128(dst, o);
        }
    }
}

extern "C" void kernel_launch(void* const* d_in, const int* in_sizes, int n_in,
                              void* d_out, int out_size)
{
    const float* node_feats = (const float*)d_in[0];
    const int*   senders    = (const int*)d_in[1];
    const int*   receivers  = (const int*)d_in[2];
    const float* W          = (const float*)d_in[3];
    const float* b          = (const float*)d_in[4];
    float*       out        = (float*)d_out;

    const int n_nodes = in_sizes[0] / D_FEAT;
    const int n_edges = in_sizes[1];

    static bool attr_set = false;
    if (!attr_set) {
        cudaFuncSetAttribute(precompute_P_kernel,
                             cudaFuncAttributeMaxDynamicSharedMemorySize, PRE_SMEM);
        attr_set = true;
    }

    const int pre_grid = (n_nodes + PM - 1) / PM;
    precompute_P_kernel<<<pre_grid, 256, PRE_SMEM>>>(node_feats, W, b, n_nodes);

    const int warps_needed = (n_edges + 7) / 8;
    const int edge_grid = (warps_needed + 7) / 8;     // 8 warps per block
    edge_kernel<<<edge_grid, 256>>>(senders, receivers, out, n_edges);
}